// round 3
// baseline (speedup 1.0000x reference)
#include <cuda_runtime.h>
#include <cuda_bf16.h>

// ---------------------------------------------------------------------------
// Problem constants (fixed by setup_inputs)
// ---------------------------------------------------------------------------
// B=64, N=4096, x_dim=256, h_dim=256, g_dim=512, Hd(hidden)=512, K=32, n=2048
#define BB     64
#define NTOT   4096
#define XD     256
#define HDIM   256
#define GDIM   512
#define HID    512
#define KC     32
#define NTOK   2048            // n
#define NH     (NTOK + 1)      // tokens using h-MLP: 0..2048  (2049)
#define NQ     (NTOT - NH)     // tokens using q-MLP: 2049..4095 (2047)
#define ROWS_HK (BB * (KC + 1))   // 2112  (Rh rows: K clusters + token-n row)
#define ROWS_H  (BB * (2*KC + 1)) // 4160
#define ROWS_E  (BB * (KC + 1))   // 2112
#define QCHUNK 8

// ---------------------------------------------------------------------------
// Scratch (device globals; no allocations allowed)
// ---------------------------------------------------------------------------
// Offsets into one big buffer (in floats)
constexpr long long OFF_Y   = 0;                                         // [B][4096][512] relu acts
constexpr long long OFF_RH  = OFF_Y   + (long long)BB*NTOT*HID;          // [B][33][512]
constexpr long long OFF_RQP = OFF_RH  + (long long)BB*(KC+1)*HID;        // [8][B][512]
constexpr long long OFF_RQ  = OFF_RQP + (long long)QCHUNK*BB*HID;        // [B][512]
constexpr long long OFF_HK  = OFF_RQ  + (long long)BB*HID;               // [B][33][256]
constexpr long long OFF_H   = OFF_HK  + (long long)BB*(KC+1)*HDIM;       // [B][65][256]
constexpr long long OFF_G1  = OFF_H   + (long long)BB*(2*KC+1)*HDIM;     // [B*65][512]
constexpr long long OFF_GS  = OFF_G1  + (long long)ROWS_H*HID;           // [B*65][512]
constexpr long long OFF_S   = OFF_GS  + (long long)ROWS_H*GDIM;          // [B][512]
constexpr long long OFF_Q   = OFF_S   + (long long)BB*GDIM;              // [B][256]
constexpr long long OFF_UU  = OFF_Q   + (long long)BB*HDIM;              // [B*33][768]
constexpr long long OFF_EH  = OFF_UU  + (long long)ROWS_E*(GDIM+HDIM);   // [B*33][512]
constexpr long long OFF_RS  = OFF_EH  + (long long)ROWS_E*HID;           // rowscale [2112]
constexpr long long SCRATCH_TOTAL = OFF_RS + ROWS_HK;

__device__ float g_buf[SCRATCH_TOTAL];
__device__ int   g_order[NTOK];
__device__ int   g_starts[KC];
__device__ int   g_counts[KC];
__device__ float g_countsf[KC];

// ---------------------------------------------------------------------------
// Counting sort of cs0 (single CTA, ballot-based stable fill — deterministic)
// ---------------------------------------------------------------------------
__global__ void build_order_kernel(const int* __restrict__ cs) {
    __shared__ int s_cnt[KC];
    int tid = threadIdx.x, lane = tid & 31, w = tid >> 5;
    if (tid < KC) s_cnt[tid] = 0;
    __syncthreads();
    for (int i = tid; i < NTOK; i += blockDim.x) atomicAdd(&s_cnt[cs[i]], 1);
    __syncthreads();
    if (tid == 0) {
        int run = 0;
        for (int k = 0; k < KC; k++) {
            g_starts[k] = run; g_counts[k] = s_cnt[k];
            g_countsf[k] = (float)s_cnt[k]; run += s_cnt[k];
        }
    }
    __syncthreads();
    if (w < KC) {
        int base = g_starts[w];
        for (int i0 = 0; i0 < NTOK; i0 += 32) {
            int t = i0 + lane;
            int c = cs[t];
            unsigned m = __ballot_sync(0xffffffffu, c == w);
            if (c == w) g_order[base + __popc(m & ((1u << lane) - 1))] = t;
            base += __popc(m);
        }
    }
}

__global__ void build_rowscale_kernel() {
    int i = blockIdx.x * blockDim.x + threadIdx.x;
    if (i < ROWS_HK) {
        int k = i % (KC + 1);
        g_buf[OFF_RS + i] = (k < KC) ? g_countsf[k] : 1.0f;
    }
}

// ---------------------------------------------------------------------------
// Tiled SGEMM: C = act( A @ Bw + scale(m)*bias ), A row-major [M,lda],
// Bw row-major [K,ldb], optional per-row bias scale, batched in z.
// Tile 128x64, 256 threads, 8x4 per thread, BK=16.
// ---------------------------------------------------------------------------
#define GBM 128
#define GBN 64
#define GBK 16
__global__ void __launch_bounds__(256) sgemm_kernel(
    const float* __restrict__ Aext, long long aOff,
    const float* __restrict__ Bw, const float* __restrict__ bias,
    int useRowscale, float biasScale, long long cOff,
    int M, int N, int K, int lda, int ldb, int ldc,
    long long aStride, long long cStride, int relu)
{
    const float* A = (Aext ? Aext : (const float*)g_buf) + aOff
                     + (long long)blockIdx.z * aStride;
    float* C = g_buf + cOff + (long long)blockIdx.z * cStride;

    int tidx = threadIdx.x;
    int tx = tidx & 15;   // N dir (x4)
    int ty = tidx >> 4;   // M dir (x8)
    int m0 = blockIdx.y * GBM;
    int n0 = blockIdx.x * GBN;

    __shared__ float As[GBK][GBM];
    __shared__ float Bs[GBK][GBN];

    float acc[8][4];
#pragma unroll
    for (int i = 0; i < 8; i++)
#pragma unroll
        for (int j = 0; j < 4; j++) acc[i][j] = 0.0f;

    for (int k0 = 0; k0 < K; k0 += GBK) {
        // A tile 128x16 = 512 float4; 2 per thread, transpose into As[k][m]
#pragma unroll
        for (int l = 0; l < 2; l++) {
            int idx = tidx * 2 + l;
            int r = idx >> 2;
            int kq = (idx & 3) * 4;
            float4 v = make_float4(0.f, 0.f, 0.f, 0.f);
            int m = m0 + r;
            if (m < M) v = *(const float4*)(A + (long long)m * lda + k0 + kq);
            As[kq + 0][r] = v.x; As[kq + 1][r] = v.y;
            As[kq + 2][r] = v.z; As[kq + 3][r] = v.w;
        }
        // B tile 16x64 = 256 float4; 1 per thread
        {
            int r = tidx >> 4;
            int c = (tidx & 15) * 4;
            *(float4*)&Bs[r][c] = *(const float4*)(Bw + (long long)(k0 + r) * ldb + n0 + c);
        }
        __syncthreads();
#pragma unroll
        for (int kk = 0; kk < GBK; kk++) {
            float4 a0 = *(const float4*)&As[kk][ty * 8];
            float4 a1 = *(const float4*)&As[kk][ty * 8 + 4];
            float4 b0 = *(const float4*)&Bs[kk][tx * 4];
            float a[8] = {a0.x, a0.y, a0.z, a0.w, a1.x, a1.y, a1.z, a1.w};
            float b[4] = {b0.x, b0.y, b0.z, b0.w};
#pragma unroll
            for (int i = 0; i < 8; i++)
#pragma unroll
                for (int j = 0; j < 4; j++) acc[i][j] = fmaf(a[i], b[j], acc[i][j]);
        }
        __syncthreads();
    }

    const float* rowscale = useRowscale ? (const float*)g_buf + OFF_RS : nullptr;
#pragma unroll
    for (int i = 0; i < 8; i++) {
        int m = m0 + ty * 8 + i;
        if (m >= M) continue;
        float rs = biasScale * (rowscale ? rowscale[m] : 1.0f);
#pragma unroll
        for (int j = 0; j < 4; j++) {
            int nn = n0 + tx * 4 + j;
            float v = acc[i][j];
            if (bias) v += rs * bias[nn];
            if (relu) v = fmaxf(v, 0.0f);
            C[(long long)m * ldc + nn] = v;
        }
    }
}

// ---------------------------------------------------------------------------
// Cluster / Q reduction over Y (deterministic fixed-order sums)
// grid (KC + 1 + QCHUNK, B), block 512 (one thread per feature)
// ---------------------------------------------------------------------------
__global__ void reduce_kernel() {
    int b = blockIdx.y;
    int x = blockIdx.x;
    int f = threadIdx.x;
    const float* Yb = g_buf + OFF_Y + (long long)b * NTOT * HID;

    if (x < KC) {
        int s = g_starts[x], c = g_counts[x];
        float a0 = 0.f, a1 = 0.f, a2 = 0.f, a3 = 0.f;
        int i = 0;
        for (; i + 4 <= c; i += 4) {
            a0 += Yb[(long long)g_order[s + i + 0] * HID + f];
            a1 += Yb[(long long)g_order[s + i + 1] * HID + f];
            a2 += Yb[(long long)g_order[s + i + 2] * HID + f];
            a3 += Yb[(long long)g_order[s + i + 3] * HID + f];
        }
        for (; i < c; i++) a0 += Yb[(long long)g_order[s + i] * HID + f];
        g_buf[OFF_RH + ((long long)b * (KC + 1) + x) * HID + f] = (a0 + a1) + (a2 + a3);
    } else if (x == KC) {
        // token n's relu activations (hn path)
        g_buf[OFF_RH + ((long long)b * (KC + 1) + KC) * HID + f] =
            Yb[(long long)NTOK * HID + f];
    } else {
        int c = x - KC - 1;
        int t0 = NH + c * 256;
        int t1 = min(NTOT, t0 + 256);
        float a0 = 0.f, a1 = 0.f, a2 = 0.f, a3 = 0.f;
        int t = t0;
        for (; t + 4 <= t1; t += 4) {
            a0 += Yb[(long long)(t + 0) * HID + f];
            a1 += Yb[(long long)(t + 1) * HID + f];
            a2 += Yb[(long long)(t + 2) * HID + f];
            a3 += Yb[(long long)(t + 3) * HID + f];
        }
        for (; t < t1; t++) a0 += Yb[(long long)t * HID + f];
        g_buf[OFF_RQP + ((long long)c * BB + b) * HID + f] = (a0 + a1) + (a2 + a3);
    }
}

__global__ void reduce_q_kernel() {  // grid B, block 512
    int b = blockIdx.x, f = threadIdx.x;
    float acc = 0.f;
#pragma unroll
    for (int c = 0; c < QCHUNK; c++)
        acc += g_buf[OFF_RQP + ((long long)c * BB + b) * HID + f];
    g_buf[OFF_RQ + (long long)b * HID + f] = acc;
}

// H[b][j][f]: j<K: Hk[j]; K<=j<2K: Hk[j-K]+hn; j==2K: hn.  grid B*65, block 256
__global__ void build_H_kernel() {
    int row = blockIdx.x;
    int b = row / (2 * KC + 1), j = row % (2 * KC + 1);
    int f = threadIdx.x;
    const float* Hk = g_buf + OFF_HK + (long long)b * (KC + 1) * HDIM;
    float hn = Hk[KC * HDIM + f];
    float v = (j < KC) ? Hk[j * HDIM + f]
            : (j < 2 * KC) ? Hk[(j - KC) * HDIM + f] + hn
            : hn;
    g_buf[OFF_H + (long long)row * HDIM + f] = v;
}

__global__ void compute_S_kernel() {  // grid B, block 512
    int b = blockIdx.x, f = threadIdx.x;
    const float* gsb = g_buf + OFF_GS + (long long)b * (2 * KC + 1) * GDIM;
    float acc = 0.f;
#pragma unroll
    for (int k = 0; k < KC; k++) acc += gsb[(long long)k * GDIM + f];
    g_buf[OFF_S + (long long)b * GDIM + f] = acc;
}

// uu[b*33+j][0:512] = G, [512:768] = Q[b].  grid B*33, block 768
__global__ void build_uu_kernel() {
    int row = blockIdx.x;
    int b = row / (KC + 1), j = row % (KC + 1);
    int f = threadIdx.x;
    float v;
    if (f < GDIM) {
        float S = g_buf[OFF_S + (long long)b * GDIM + f];
        const float* gsb = g_buf + OFF_GS + (long long)b * (2 * KC + 1) * GDIM;
        if (j < KC) v = S - gsb[(long long)j * GDIM + f] + gsb[(long long)(KC + j) * GDIM + f];
        else        v = S + gsb[(long long)(2 * KC) * GDIM + f];
    } else {
        v = g_buf[OFF_Q + (long long)b * HDIM + (f - GDIM)];
    }
    g_buf[OFF_UU + (long long)row * (GDIM + HDIM) + f] = v;
}

// E[row] = dot(EH[row], We2); also writes the ones-mask. 8 warps/block.
__global__ void final_kernel(const float* __restrict__ We2, float* __restrict__ out) {
    int w = (blockIdx.x * blockDim.x + threadIdx.x) >> 5;
    int lane = threadIdx.x & 31;
    if (w >= ROWS_E) return;
    const float* r = g_buf + OFF_EH + (long long)w * HID;
    float acc = 0.f;
    for (int i = lane; i < HID; i += 32) acc += r[i] * We2[i];
#pragma unroll
    for (int o = 16; o; o >>= 1) acc += __shfl_xor_sync(0xffffffffu, acc, o);
    if (lane == 0) {
        out[w] = acc;              // E  (B, K+1) row-major
        out[ROWS_E + w] = 1.0f;    // G_mask ones
    }
}

// ---------------------------------------------------------------------------
// Launch
// ---------------------------------------------------------------------------
static inline void launch_sgemm(const float* Aext, long long aOff,
                                const float* Bw, const float* bias,
                                int useRS, float biasScale, long long cOff,
                                int M, int N, int K, int lda, int ldb, int ldc,
                                long long aStride, long long cStride, int Z, int relu)
{
    dim3 grid(N / GBN, (M + GBM - 1) / GBM, Z);
    sgemm_kernel<<<grid, 256>>>(Aext, aOff, Bw, bias, useRS, biasScale, cOff,
                                M, N, K, lda, ldb, ldc, aStride, cStride, relu);
}

extern "C" void kernel_launch(void* const* d_in, const int* in_sizes, int n_in,
                              void* d_out, int out_size) {
    const float* data = (const float*)d_in[0];
    const int*   cs   = (const int*)  d_in[1];
    const float* Wh1 = (const float*)d_in[3];
    const float* bh1 = (const float*)d_in[4];
    const float* Wh2 = (const float*)d_in[5];
    const float* bh2 = (const float*)d_in[6];
    const float* Wq1 = (const float*)d_in[7];
    const float* bq1 = (const float*)d_in[8];
    const float* Wq2 = (const float*)d_in[9];
    const float* bq2 = (const float*)d_in[10];
    const float* Wg1 = (const float*)d_in[11];
    const float* bg1 = (const float*)d_in[12];
    const float* Wg2 = (const float*)d_in[13];
    const float* bg2 = (const float*)d_in[14];
    const float* We1 = (const float*)d_in[15];
    const float* be1 = (const float*)d_in[16];
    const float* We2 = (const float*)d_in[17];
    float* out = (float*)d_out;

    // 1) cluster counting-sort + bias row scales
    build_order_kernel<<<1, 1024>>>(cs);
    build_rowscale_kernel<<<(ROWS_HK + 255) / 256, 256>>>();

    // 2) main fused layer-1 GEMMs + ReLU -> Y  (dominant work)
    // h-phase: tokens [0, 2049) of each batch
    launch_sgemm(data, 0, Wh1, bh1, 0, 1.0f, OFF_Y,
                 NH, HID, XD, XD, HID, HID,
                 (long long)NTOT * XD, (long long)NTOT * HID, BB, 1);
    // q-phase: tokens [2049, 4096)
    launch_sgemm(data, (long long)NH * XD, Wq1, bq1, 0, 1.0f,
                 OFF_Y + (long long)NH * HID,
                 NQ, HID, XD, XD, HID, HID,
                 (long long)NTOT * XD, (long long)NTOT * HID, BB, 1);

    // 3) deterministic cluster / Q reductions over Y
    reduce_kernel<<<dim3(KC + 1 + QCHUNK, BB), 512>>>();
    reduce_q_kernel<<<BB, 512>>>();

    // 4) Hk = Rh @ Wh2 + counts*bh2  (row 32 per batch = hn, scale 1)
    launch_sgemm(nullptr, OFF_RH, Wh2, bh2, 1, 1.0f, OFF_HK,
                 ROWS_HK, HDIM, HID, HID, HDIM, HDIM, 0, 0, 1, 0);
    // 5) Q = Rq @ Wq2 + 2047*bq2
    launch_sgemm(nullptr, OFF_RQ, Wq2, bq2, 0, (float)NQ, OFF_Q,
                 BB, HDIM, HID, HID, HDIM, HDIM, 0, 0, 1, 0);

    // 6) g-MLP on H
    build_H_kernel<<<ROWS_H, HDIM>>>();
    launch_sgemm(nullptr, OFF_H, Wg1, bg1, 0, 1.0f, OFF_G1,
                 ROWS_H, HID, HDIM, HDIM, HID, HID, 0, 0, 1, 1);
    launch_sgemm(nullptr, OFF_G1, Wg2, bg2, 0, 1.0f, OFF_GS,
                 ROWS_H, GDIM, HID, HID, GDIM, GDIM, 0, 0, 1, 0);

    // 7) combine G + Q -> uu, then energy MLP
    compute_S_kernel<<<BB, GDIM>>>();
    build_uu_kernel<<<ROWS_E, GDIM + HDIM>>>();
    launch_sgemm(nullptr, OFF_UU, We1, be1, 0, 1.0f, OFF_EH,
                 ROWS_E, HID, GDIM + HDIM, GDIM + HDIM, HID, HID, 0, 0, 1, 1);
    final_kernel<<<(ROWS_E * 32 + 255) / 256, 256>>>(We2, out);
}

// round 8
// speedup vs baseline: 1.3249x; 1.3249x over previous
#include <cuda_runtime.h>
#include <cuda_bf16.h>
#include <mma.h>
#include <cstdint>

using namespace nvcuda;

// ---------------------------------------------------------------------------
// Problem constants (fixed by setup_inputs)
// ---------------------------------------------------------------------------
#define BB     64
#define NTOT   4096
#define XD     256
#define HDIM   256
#define GDIM   512
#define HID    512
#define KC     32
#define NTOK   2048
#define NH     (NTOK + 1)      // h tokens 0..2048 (2049)
#define NQ     (NTOT - NH)     // q tokens 2049..4095 (2047)
#define ROWS_HK (BB * (KC + 1))
#define ROWS_H  (BB * (2*KC + 1))
#define ROWS_E  (BB * (KC + 1))
#define QCHUNK 8

// ---------------------------------------------------------------------------
// Scratch
// ---------------------------------------------------------------------------
constexpr long long OFF_Y   = 0;
constexpr long long OFF_RH  = OFF_Y   + (long long)BB*NTOT*HID;
constexpr long long OFF_RQP = OFF_RH  + (long long)BB*(KC+1)*HID;
constexpr long long OFF_RQ  = OFF_RQP + (long long)QCHUNK*BB*HID;
constexpr long long OFF_HK  = OFF_RQ  + (long long)BB*HID;
constexpr long long OFF_H   = OFF_HK  + (long long)BB*(KC+1)*HDIM;
constexpr long long OFF_G1  = OFF_H   + (long long)BB*(2*KC+1)*HDIM;
constexpr long long OFF_GS  = OFF_G1  + (long long)ROWS_H*HID;
constexpr long long OFF_S   = OFF_GS  + (long long)ROWS_H*GDIM;
constexpr long long OFF_Q   = OFF_S   + (long long)BB*GDIM;
constexpr long long OFF_UU  = OFF_Q   + (long long)BB*HDIM;
constexpr long long OFF_EH  = OFF_UU  + (long long)ROWS_E*(GDIM+HDIM);
constexpr long long OFF_RS  = OFF_EH  + (long long)ROWS_E*HID;
constexpr long long SCRATCH_TOTAL = OFF_RS + ROWS_HK;

__device__ float g_buf[SCRATCH_TOTAL];
__device__ int   g_order[NTOK];
__device__ int   g_starts[KC];
__device__ int   g_counts[KC];
__device__ float g_countsf[KC];
// transposed, bf16-split weights: [0]=h_hi [1]=h_lo [2]=q_hi [3]=q_lo, each [512][256]
__device__ __nv_bfloat16 g_wt[4][HID * XD];

// ---------------------------------------------------------------------------
// Weight prep: W[256][512] fp32 -> WT hi/lo bf16 [512][256]
// ---------------------------------------------------------------------------
__global__ void prep_weights_kernel(const float* __restrict__ Wh1, const float* __restrict__ Wq1) {
    int i = blockIdx.x * blockDim.x + threadIdx.x;
    if (i >= XD * HID) return;
    int k = i / HID, n = i % HID;
    float v = Wh1[i];
    __nv_bfloat16 hi = __float2bfloat16(v);
    __nv_bfloat16 lo = __float2bfloat16(v - __bfloat162float(hi));
    g_wt[0][n * XD + k] = hi; g_wt[1][n * XD + k] = lo;
    v = Wq1[i];
    hi = __float2bfloat16(v);
    lo = __float2bfloat16(v - __bfloat162float(hi));
    g_wt[2][n * XD + k] = hi; g_wt[3][n * XD + k] = lo;
}

// ---------------------------------------------------------------------------
// Layer-1 wmma GEMM (portable HMMA path; tcgen05 unavailable on sm_103 target)
// Y[token] = relu(data[token] @ W1 + b1), bf16 hi/lo split, 3-term.
// grid (4 nblk, 33 tile, 64 batch), 512 threads (16 warps, warp tile 32x32).
// CTA tile M=128 x N=128, K=256 in 4 chunks of 64.
// ---------------------------------------------------------------------------
#define LDA   72            // padded bf16 row stride (64 + 8)
#define LDS_F 132           // padded f32 staging stride (128 + 4)
#define A_HI_OFF  0
#define A_LO_OFF  18432
#define B_HI_OFF  36864
#define B_LO_OFF  55296
#define L1_SMEM   73728     // max(4*18432, 128*132*4=67584)

__global__ void __launch_bounds__(512) layer1_wmma_kernel(
    const float* __restrict__ data,
    const float* __restrict__ bh, const float* __restrict__ bq)
{
    extern __shared__ char smem[];
    __nv_bfloat16* sAhi = (__nv_bfloat16*)(smem + A_HI_OFF);
    __nv_bfloat16* sAlo = (__nv_bfloat16*)(smem + A_LO_OFF);
    __nv_bfloat16* sBhi = (__nv_bfloat16*)(smem + B_HI_OFF);
    __nv_bfloat16* sBlo = (__nv_bfloat16*)(smem + B_LO_OFF);
    float* stage = (float*)smem;

    const int tid = threadIdx.x;
    const int wid = tid >> 5;
    const int wm = wid >> 2;          // 0..3 (M direction, 32 rows each)
    const int wn = wid & 3;           // 0..3 (N direction, 32 cols each)

    const int nb = blockIdx.x, tile = blockIdx.y, b = blockIdx.z;
    const bool is_h = tile < 17;
    const int tile_start = is_h ? tile * 128 : NH + (tile - 17) * 128;
    const int token_lim = is_h ? NTOK : (NTOT - 1);     // inclusive
    const int n0 = nb * 128;
    const __nv_bfloat16* WThi = is_h ? g_wt[0] : g_wt[2];
    const __nv_bfloat16* WTlo = is_h ? g_wt[1] : g_wt[3];
    const float* bias = is_h ? bh : bq;

    wmma::fragment<wmma::accumulator, 16, 16, 16, float> acc[2][2];
#pragma unroll
    for (int i = 0; i < 2; i++)
#pragma unroll
        for (int j = 0; j < 2; j++) wmma::fill_fragment(acc[i][j], 0.0f);

    const int r = tid >> 2;           // 0..127 (row for loads / epilogue)
    {
        // clamp for A loads
    }
    int token_ld = tile_start + r;
    if (token_ld > NTOT - 1) token_ld = NTOT - 1;
    const float* arow = data + ((long long)b * NTOT + token_ld) * XD;

    for (int ch = 0; ch < 4; ch++) {
        const int k0 = ch * 64;
        // ---- stage A: 128 x 64 fp32 -> bf16 hi/lo (each thread: 16 k-values)
        {
            const int cq = (tid & 3) * 16;
            const float* src = arow + k0 + cq;
#pragma unroll
            for (int j = 0; j < 4; j++) {
                float4 v = *(const float4*)(src + j * 4);
                int base = r * LDA + cq + j * 4;
                __nv_bfloat16 h0 = __float2bfloat16(v.x), h1 = __float2bfloat16(v.y),
                              h2 = __float2bfloat16(v.z), h3 = __float2bfloat16(v.w);
                sAhi[base + 0] = h0; sAhi[base + 1] = h1;
                sAhi[base + 2] = h2; sAhi[base + 3] = h3;
                sAlo[base + 0] = __float2bfloat16(v.x - __bfloat162float(h0));
                sAlo[base + 1] = __float2bfloat16(v.y - __bfloat162float(h1));
                sAlo[base + 2] = __float2bfloat16(v.z - __bfloat162float(h2));
                sAlo[base + 3] = __float2bfloat16(v.w - __bfloat162float(h3));
            }
        }
        // ---- stage B: 128 n-rows x 64 k (pre-split bf16): 2 x uint4 per thread
        {
            const int seg = (tid & 3) * 16;
            const __nv_bfloat16* srcH = WThi + (long long)(n0 + r) * XD + k0 + seg;
            const __nv_bfloat16* srcL = WTlo + (long long)(n0 + r) * XD + k0 + seg;
            int base = r * LDA + seg;
            *(uint4*)&sBhi[base]     = *(const uint4*)(srcH);
            *(uint4*)&sBhi[base + 8] = *(const uint4*)(srcH + 8);
            *(uint4*)&sBlo[base]     = *(const uint4*)(srcL);
            *(uint4*)&sBlo[base + 8] = *(const uint4*)(srcL + 8);
        }
        __syncthreads();

        // ---- compute: 4 k-steps of 16
#pragma unroll
        for (int ks = 0; ks < 4; ks++) {
            const int ko = ks * 16;
            wmma::fragment<wmma::matrix_a, 16, 16, 16, __nv_bfloat16, wmma::row_major> aH[2], aL[2];
            wmma::fragment<wmma::matrix_b, 16, 16, 16, __nv_bfloat16, wmma::col_major> bH[2], bL[2];
#pragma unroll
            for (int i = 0; i < 2; i++) {
                wmma::load_matrix_sync(aH[i], &sAhi[(wm * 32 + i * 16) * LDA + ko], LDA);
                wmma::load_matrix_sync(aL[i], &sAlo[(wm * 32 + i * 16) * LDA + ko], LDA);
            }
#pragma unroll
            for (int j = 0; j < 2; j++) {
                wmma::load_matrix_sync(bH[j], &sBhi[(wn * 32 + j * 16) * LDA + ko], LDA);
                wmma::load_matrix_sync(bL[j], &sBlo[(wn * 32 + j * 16) * LDA + ko], LDA);
            }
#pragma unroll
            for (int i = 0; i < 2; i++)
#pragma unroll
                for (int j = 0; j < 2; j++) {
                    wmma::mma_sync(acc[i][j], aH[i], bH[j], acc[i][j]);
                    wmma::mma_sync(acc[i][j], aH[i], bL[j], acc[i][j]);
                    wmma::mma_sync(acc[i][j], aL[i], bH[j], acc[i][j]);
                }
        }
        __syncthreads();
    }

    // ---- epilogue: stage accumulators, add bias + relu, write Y
#pragma unroll
    for (int i = 0; i < 2; i++)
#pragma unroll
        for (int j = 0; j < 2; j++)
            wmma::store_matrix_sync(&stage[(wm * 32 + i * 16) * LDS_F + wn * 32 + j * 16],
                                    acc[i][j], LDS_F, wmma::mem_row_major);
    __syncthreads();

    const int token = tile_start + r;
    if (token <= token_lim) {
        const int c0 = (tid & 3) * 32;
        float* yrow = g_buf + OFF_Y + ((long long)b * NTOT + token) * HID + n0;
#pragma unroll
        for (int u = 0; u < 8; u++) {
            int c = c0 + u * 4;
            float4 v = *(float4*)&stage[r * LDS_F + c];
            float4 o;
            o.x = fmaxf(v.x + bias[n0 + c + 0], 0.f);
            o.y = fmaxf(v.y + bias[n0 + c + 1], 0.f);
            o.z = fmaxf(v.z + bias[n0 + c + 2], 0.f);
            o.w = fmaxf(v.w + bias[n0 + c + 3], 0.f);
            *(float4*)(yrow + c) = o;
        }
    }
}

// ---------------------------------------------------------------------------
// Counting sort of cs0 (deterministic)
// ---------------------------------------------------------------------------
__global__ void build_order_kernel(const int* __restrict__ cs) {
    __shared__ int s_cnt[KC];
    int tid = threadIdx.x, lane = tid & 31, w = tid >> 5;
    if (tid < KC) s_cnt[tid] = 0;
    __syncthreads();
    for (int i = tid; i < NTOK; i += blockDim.x) atomicAdd(&s_cnt[cs[i]], 1);
    __syncthreads();
    if (tid == 0) {
        int run = 0;
        for (int k = 0; k < KC; k++) {
            g_starts[k] = run; g_counts[k] = s_cnt[k];
            g_countsf[k] = (float)s_cnt[k]; run += s_cnt[k];
        }
    }
    __syncthreads();
    if (w < KC) {
        int base = g_starts[w];
        for (int i0 = 0; i0 < NTOK; i0 += 32) {
            int t = i0 + lane;
            int c = cs[t];
            unsigned m = __ballot_sync(0xffffffffu, c == w);
            if (c == w) g_order[base + __popc(m & ((1u << lane) - 1))] = t;
            base += __popc(m);
        }
    }
}

__global__ void build_rowscale_kernel() {
    int i = blockIdx.x * blockDim.x + threadIdx.x;
    if (i < ROWS_HK) {
        int k = i % (KC + 1);
        g_buf[OFF_RS + i] = (k < KC) ? g_countsf[k] : 1.0f;
    }
}

// ---------------------------------------------------------------------------
// SIMT SGEMM for small layers
// ---------------------------------------------------------------------------
#define GBM 128
#define GBN 64
#define GBK 16
__global__ void __launch_bounds__(256) sgemm_kernel(
    const float* __restrict__ Aext, long long aOff,
    const float* __restrict__ Bw, const float* __restrict__ bias,
    int useRowscale, float biasScale, long long cOff,
    int M, int N, int K, int lda, int ldb, int ldc,
    long long aStride, long long cStride, int relu)
{
    const float* A = (Aext ? Aext : (const float*)g_buf) + aOff
                     + (long long)blockIdx.z * aStride;
    float* C = g_buf + cOff + (long long)blockIdx.z * cStride;

    int tidx = threadIdx.x;
    int tx = tidx & 15;
    int ty = tidx >> 4;
    int m0 = blockIdx.y * GBM;
    int n0 = blockIdx.x * GBN;

    __shared__ float As[GBK][GBM];
    __shared__ float Bs[GBK][GBN];

    float acc[8][4];
#pragma unroll
    for (int i = 0; i < 8; i++)
#pragma unroll
        for (int j = 0; j < 4; j++) acc[i][j] = 0.0f;

    for (int k0 = 0; k0 < K; k0 += GBK) {
#pragma unroll
        for (int l = 0; l < 2; l++) {
            int idx = tidx * 2 + l;
            int r = idx >> 2;
            int kq = (idx & 3) * 4;
            float4 v = make_float4(0.f, 0.f, 0.f, 0.f);
            int m = m0 + r;
            if (m < M) v = *(const float4*)(A + (long long)m * lda + k0 + kq);
            As[kq + 0][r] = v.x; As[kq + 1][r] = v.y;
            As[kq + 2][r] = v.z; As[kq + 3][r] = v.w;
        }
        {
            int r = tidx >> 4;
            int c = (tidx & 15) * 4;
            *(float4*)&Bs[r][c] = *(const float4*)(Bw + (long long)(k0 + r) * ldb + n0 + c);
        }
        __syncthreads();
#pragma unroll
        for (int kk = 0; kk < GBK; kk++) {
            float4 a0 = *(const float4*)&As[kk][ty * 8];
            float4 a1 = *(const float4*)&As[kk][ty * 8 + 4];
            float4 b0 = *(const float4*)&Bs[kk][tx * 4];
            float a[8] = {a0.x, a0.y, a0.z, a0.w, a1.x, a1.y, a1.z, a1.w};
            float br[4] = {b0.x, b0.y, b0.z, b0.w};
#pragma unroll
            for (int i = 0; i < 8; i++)
#pragma unroll
                for (int j = 0; j < 4; j++) acc[i][j] = fmaf(a[i], br[j], acc[i][j]);
        }
        __syncthreads();
    }

    const float* rowscale = useRowscale ? (const float*)g_buf + OFF_RS : nullptr;
#pragma unroll
    for (int i = 0; i < 8; i++) {
        int m = m0 + ty * 8 + i;
        if (m >= M) continue;
        float rs = biasScale * (rowscale ? rowscale[m] : 1.0f);
#pragma unroll
        for (int j = 0; j < 4; j++) {
            int nn = n0 + tx * 4 + j;
            float v = acc[i][j];
            if (bias) v += rs * bias[nn];
            if (relu) v = fmaxf(v, 0.0f);
            C[(long long)m * ldc + nn] = v;
        }
    }
}

// ---------------------------------------------------------------------------
// Reductions / glue
// ---------------------------------------------------------------------------
__global__ void reduce_kernel() {
    int b = blockIdx.y;
    int x = blockIdx.x;
    int f = threadIdx.x;
    const float* Yb = g_buf + OFF_Y + (long long)b * NTOT * HID;

    if (x < KC) {
        int s = g_starts[x], c = g_counts[x];
        float a0 = 0.f, a1 = 0.f, a2 = 0.f, a3 = 0.f;
        int i = 0;
        for (; i + 4 <= c; i += 4) {
            a0 += Yb[(long long)g_order[s + i + 0] * HID + f];
            a1 += Yb[(long long)g_order[s + i + 1] * HID + f];
            a2 += Yb[(long long)g_order[s + i + 2] * HID + f];
            a3 += Yb[(long long)g_order[s + i + 3] * HID + f];
        }
        for (; i < c; i++) a0 += Yb[(long long)g_order[s + i] * HID + f];
        g_buf[OFF_RH + ((long long)b * (KC + 1) + x) * HID + f] = (a0 + a1) + (a2 + a3);
    } else if (x == KC) {
        g_buf[OFF_RH + ((long long)b * (KC + 1) + KC) * HID + f] =
            Yb[(long long)NTOK * HID + f];
    } else {
        int c = x - KC - 1;
        int t0 = NH + c * 256;
        int t1 = min(NTOT, t0 + 256);
        float a0 = 0.f, a1 = 0.f, a2 = 0.f, a3 = 0.f;
        int t = t0;
        for (; t + 4 <= t1; t += 4) {
            a0 += Yb[(long long)(t + 0) * HID + f];
            a1 += Yb[(long long)(t + 1) * HID + f];
            a2 += Yb[(long long)(t + 2) * HID + f];
            a3 += Yb[(long long)(t + 3) * HID + f];
        }
        for (; t < t1; t++) a0 += Yb[(long long)t * HID + f];
        g_buf[OFF_RQP + ((long long)c * BB + b) * HID + f] = (a0 + a1) + (a2 + a3);
    }
}

__global__ void reduce_q_kernel() {
    int b = blockIdx.x, f = threadIdx.x;
    float acc = 0.f;
#pragma unroll
    for (int c = 0; c < QCHUNK; c++)
        acc += g_buf[OFF_RQP + ((long long)c * BB + b) * HID + f];
    g_buf[OFF_RQ + (long long)b * HID + f] = acc;
}

__global__ void build_H_kernel() {
    int row = blockIdx.x;
    int b = row / (2 * KC + 1), j = row % (2 * KC + 1);
    int f = threadIdx.x;
    const float* Hk = g_buf + OFF_HK + (long long)b * (KC + 1) * HDIM;
    float hn = Hk[KC * HDIM + f];
    float v = (j < KC) ? Hk[j * HDIM + f]
            : (j < 2 * KC) ? Hk[(j - KC) * HDIM + f] + hn
            : hn;
    g_buf[OFF_H + (long long)row * HDIM + f] = v;
}

__global__ void compute_S_kernel() {
    int b = blockIdx.x, f = threadIdx.x;
    const float* gsb = g_buf + OFF_GS + (long long)b * (2 * KC + 1) * GDIM;
    float acc = 0.f;
#pragma unroll
    for (int k = 0; k < KC; k++) acc += gsb[(long long)k * GDIM + f];
    g_buf[OFF_S + (long long)b * GDIM + f] = acc;
}

__global__ void build_uu_kernel() {
    int row = blockIdx.x;
    int b = row / (KC + 1), j = row % (KC + 1);
    int f = threadIdx.x;
    float v;
    if (f < GDIM) {
        float S = g_buf[OFF_S + (long long)b * GDIM + f];
        const float* gsb = g_buf + OFF_GS + (long long)b * (2 * KC + 1) * GDIM;
        if (j < KC) v = S - gsb[(long long)j * GDIM + f] + gsb[(long long)(KC + j) * GDIM + f];
        else        v = S + gsb[(long long)(2 * KC) * GDIM + f];
    } else {
        v = g_buf[OFF_Q + (long long)b * HDIM + (f - GDIM)];
    }
    g_buf[OFF_UU + (long long)row * (GDIM + HDIM) + f] = v;
}

__global__ void final_kernel(const float* __restrict__ We2, float* __restrict__ out) {
    int w = (blockIdx.x * blockDim.x + threadIdx.x) >> 5;
    int lane = threadIdx.x & 31;
    if (w >= ROWS_E) return;
    const float* r = g_buf + OFF_EH + (long long)w * HID;
    float acc = 0.f;
    for (int i = lane; i < HID; i += 32) acc += r[i] * We2[i];
#pragma unroll
    for (int o = 16; o; o >>= 1) acc += __shfl_xor_sync(0xffffffffu, acc, o);
    if (lane == 0) {
        out[w] = acc;
        out[ROWS_E + w] = 1.0f;
    }
}

// ---------------------------------------------------------------------------
// Launch
// ---------------------------------------------------------------------------
static inline void launch_sgemm(const float* Aext, long long aOff,
                                const float* Bw, const float* bias,
                                int useRS, float biasScale, long long cOff,
                                int M, int N, int K, int lda, int ldb, int ldc,
                                long long aStride, long long cStride, int Z, int relu)
{
    dim3 grid(N / GBN, (M + GBM - 1) / GBM, Z);
    sgemm_kernel<<<grid, 256>>>(Aext, aOff, Bw, bias, useRS, biasScale, cOff,
                                M, N, K, lda, ldb, ldc, aStride, cStride, relu);
}

extern "C" void kernel_launch(void* const* d_in, const int* in_sizes, int n_in,
                              void* d_out, int out_size) {
    const float* data = (const float*)d_in[0];
    const int*   cs   = (const int*)  d_in[1];
    const float* Wh1 = (const float*)d_in[3];
    const float* bh1 = (const float*)d_in[4];
    const float* Wh2 = (const float*)d_in[5];
    const float* bh2 = (const float*)d_in[6];
    const float* Wq1 = (const float*)d_in[7];
    const float* bq1 = (const float*)d_in[8];
    const float* Wq2 = (const float*)d_in[9];
    const float* bq2 = (const float*)d_in[10];
    const float* Wg1 = (const float*)d_in[11];
    const float* bg1 = (const float*)d_in[12];
    const float* Wg2 = (const float*)d_in[13];
    const float* bg2 = (const float*)d_in[14];
    const float* We1 = (const float*)d_in[15];
    const float* be1 = (const float*)d_in[16];
    const float* We2 = (const float*)d_in[17];
    float* out = (float*)d_out;

    // 1) cluster counting-sort + bias row scales + weight split/transpose
    build_order_kernel<<<1, 1024>>>(cs);
    build_rowscale_kernel<<<(ROWS_HK + 255) / 256, 256>>>();
    prep_weights_kernel<<<(XD * HID + 255) / 256, 256>>>(Wh1, Wq1);

    // 2) layer-1 on wmma tensor cores (bf16 split-precision, 3-term) -> Y
    cudaFuncSetAttribute(layer1_wmma_kernel,
                         cudaFuncAttributeMaxDynamicSharedMemorySize, L1_SMEM);
    layer1_wmma_kernel<<<dim3(4, 33, BB), 512, L1_SMEM>>>(data, bh1, bq1);

    // 3) deterministic cluster / Q reductions over Y
    reduce_kernel<<<dim3(KC + 1 + QCHUNK, BB), 512>>>();
    reduce_q_kernel<<<BB, 512>>>();

    // 4) Hk = Rh @ Wh2 + counts*bh2
    launch_sgemm(nullptr, OFF_RH, Wh2, bh2, 1, 1.0f, OFF_HK,
                 ROWS_HK, HDIM, HID, HID, HDIM, HDIM, 0, 0, 1, 0);
    // 5) Q = Rq @ Wq2 + 2047*bq2
    launch_sgemm(nullptr, OFF_RQ, Wq2, bq2, 0, (float)NQ, OFF_Q,
                 BB, HDIM, HID, HID, HDIM, HDIM, 0, 0, 1, 0);

    // 6) g-MLP on H
    build_H_kernel<<<ROWS_H, HDIM>>>();
    launch_sgemm(nullptr, OFF_H, Wg1, bg1, 0, 1.0f, OFF_G1,
                 ROWS_H, HID, HDIM, HDIM, HID, HID, 0, 0, 1, 1);
    launch_sgemm(nullptr, OFF_G1, Wg2, bg2, 0, 1.0f, OFF_GS,
                 ROWS_H, GDIM, HID, HID, GDIM, GDIM, 0, 0, 1, 0);

    // 7) combine G + Q -> uu, then energy MLP
    compute_S_kernel<<<BB, GDIM>>>();
    build_uu_kernel<<<ROWS_E, GDIM + HDIM>>>();
    launch_sgemm(nullptr, OFF_UU, We1, be1, 0, 1.0f, OFF_EH,
                 ROWS_E, HID, GDIM + HDIM, GDIM + HDIM, HID, HID, 0, 0, 1, 1);
    final_kernel<<<(ROWS_E * 32 + 255) / 256, 256>>>(We2, out);
}

// round 10
// speedup vs baseline: 1.3819x; 1.0430x over previous
#include <cuda_runtime.h>
#include <cuda_bf16.h>
#include <mma.h>
#include <cstdint>

using namespace nvcuda;

// ---------------------------------------------------------------------------
// Problem constants (fixed by setup_inputs)
// ---------------------------------------------------------------------------
#define BB     64
#define NTOT   4096
#define XD     256
#define HDIM   256
#define GDIM   512
#define HID    512
#define KC     32
#define NTOK   2048
#define NH     (NTOK + 1)      // h tokens 0..2048 (2049)
#define NQ     (NTOT - NH)     // q tokens 2049..4095 (2047)
#define ROWS_HK (BB * (KC + 1))
#define ROWS_H  (BB * (2*KC + 1))
#define ROWS_E  (BB * (KC + 1))
#define QCHUNK 8

// ---------------------------------------------------------------------------
// Scratch
// ---------------------------------------------------------------------------
constexpr long long OFF_Y   = 0;
constexpr long long OFF_RH  = OFF_Y   + (long long)BB*NTOT*HID;
constexpr long long OFF_RQP = OFF_RH  + (long long)BB*(KC+1)*HID;
constexpr long long OFF_RQ  = OFF_RQP + (long long)QCHUNK*BB*HID;
constexpr long long OFF_HK  = OFF_RQ  + (long long)BB*HID;
constexpr long long OFF_H   = OFF_HK  + (long long)BB*(KC+1)*HDIM;
constexpr long long OFF_G1  = OFF_H   + (long long)BB*(2*KC+1)*HDIM;
constexpr long long OFF_GS  = OFF_G1  + (long long)ROWS_H*HID;
constexpr long long OFF_S   = OFF_GS  + (long long)ROWS_H*GDIM;
constexpr long long OFF_Q   = OFF_S   + (long long)BB*GDIM;
constexpr long long OFF_UU  = OFF_Q   + (long long)BB*HDIM;
constexpr long long OFF_EH  = OFF_UU  + (long long)ROWS_E*(GDIM+HDIM);
constexpr long long OFF_RS  = OFF_EH  + (long long)ROWS_E*HID;
constexpr long long SCRATCH_TOTAL = OFF_RS + ROWS_HK;

__device__ float g_buf[SCRATCH_TOTAL];
__device__ int   g_order[NTOK];
__device__ int   g_starts[KC];
__device__ int   g_counts[KC];
__device__ float g_countsf[KC];
// transposed, bf16-split weights: [0]=h_hi [1]=h_lo [2]=q_hi [3]=q_lo, each [512][256]
__device__ __nv_bfloat16 g_wt[4][HID * XD];
// bf16-split activations (hi/lo) of data: [B][4096][256]
__device__ __nv_bfloat16 g_ahi[(long long)BB * NTOT * XD];
__device__ __nv_bfloat16 g_alo[(long long)BB * NTOT * XD];

// ---------------------------------------------------------------------------
// cp.async helpers
// ---------------------------------------------------------------------------
__device__ __forceinline__ uint32_t smem_u32(const void* p) {
    uint32_t a;
    asm("{ .reg .u64 t; cvta.to.shared.u64 t, %1; cvt.u32.u64 %0, t; }" : "=r"(a) : "l"(p));
    return a;
}
__device__ __forceinline__ void cp16(uint32_t dst, const void* src) {
    asm volatile("cp.async.cg.shared.global [%0], [%1], 16;" :: "r"(dst), "l"(src));
}
#define CP_COMMIT() asm volatile("cp.async.commit_group;" ::: "memory")
#define CP_WAIT1()  asm volatile("cp.async.wait_group 1;" ::: "memory")
#define CP_WAIT0()  asm volatile("cp.async.wait_group 0;" ::: "memory")

// ---------------------------------------------------------------------------
// Weight prep: W[256][512] fp32 -> WT hi/lo bf16 [512][256]
// ---------------------------------------------------------------------------
__global__ void prep_weights_kernel(const float* __restrict__ Wh1, const float* __restrict__ Wq1) {
    int i = blockIdx.x * blockDim.x + threadIdx.x;
    if (i >= XD * HID) return;
    int k = i / HID, n = i % HID;
    float v = Wh1[i];
    __nv_bfloat16 hi = __float2bfloat16(v);
    __nv_bfloat16 lo = __float2bfloat16(v - __bfloat162float(hi));
    g_wt[0][n * XD + k] = hi; g_wt[1][n * XD + k] = lo;
    v = Wq1[i];
    hi = __float2bfloat16(v);
    lo = __float2bfloat16(v - __bfloat162float(hi));
    g_wt[2][n * XD + k] = hi; g_wt[3][n * XD + k] = lo;
}

// ---------------------------------------------------------------------------
// Data prep: fp32 -> bf16 hi/lo (vectorized float4 -> 2x uint2)
// ---------------------------------------------------------------------------
__global__ void prep_data_kernel(const float* __restrict__ data) {
    long long i = (long long)blockIdx.x * blockDim.x + threadIdx.x;  // float4 index
    const long long total4 = (long long)BB * NTOT * XD / 4;
    if (i >= total4) return;
    float4 v = ((const float4*)data)[i];
    __nv_bfloat16 h0 = __float2bfloat16(v.x), h1 = __float2bfloat16(v.y),
                  h2 = __float2bfloat16(v.z), h3 = __float2bfloat16(v.w);
    __nv_bfloat162 ph0; ph0.x = h0; ph0.y = h1;
    __nv_bfloat162 ph1; ph1.x = h2; ph1.y = h3;
    __nv_bfloat162 pl0, pl1;
    pl0.x = __float2bfloat16(v.x - __bfloat162float(h0));
    pl0.y = __float2bfloat16(v.y - __bfloat162float(h1));
    pl1.x = __float2bfloat16(v.z - __bfloat162float(h2));
    pl1.y = __float2bfloat16(v.w - __bfloat162float(h3));
    ((uint2*)g_ahi)[i] = make_uint2(*(uint32_t*)&ph0, *(uint32_t*)&ph1);
    ((uint2*)g_alo)[i] = make_uint2(*(uint32_t*)&pl0, *(uint32_t*)&pl1);
}

// ---------------------------------------------------------------------------
// Layer-1 wmma GEMM, cp.async double-buffered.
// Y[token] = relu(data[token] @ W1 + b1), bf16 hi/lo split, 3-term.
// grid (4 nblk, 33 tile, 64 batch), 512 threads (16 warps, warp tile 32x32).
// CTA tile M=128 x N=128, K=256 in 8 chunks of 32.
// ---------------------------------------------------------------------------
#define KCH    32
#define LDA2   40                       // padded bf16 row stride (32 + 8)
#define TILE_E (128 * LDA2)             // 5120 elements per tile
#define BUF_B  (4 * TILE_E * 2)         // bytes per buffer (Ahi,Alo,Bhi,Blo) = 40960
#define LDS_F  132                      // padded f32 staging stride (128 + 4)
#define L1_SMEM (2 * BUF_B)             // 81920 B (stage 128*132*4=67584 fits)

__global__ void __launch_bounds__(512) layer1_wmma_kernel(
    const float* __restrict__ bh, const float* __restrict__ bq)
{
    extern __shared__ char smem[];
    const uint32_t sb = smem_u32(smem);
    float* stage = (float*)smem;

    const int tid = threadIdx.x;
    const int wid = tid >> 5;
    const int wm = wid >> 2;          // 0..3 (M direction, 32 rows each)
    const int wn = wid & 3;           // 0..3 (N direction, 32 cols each)

    const int nb = blockIdx.x, tile = blockIdx.y, b = blockIdx.z;
    const bool is_h = tile < 17;
    const int tile_start = is_h ? tile * 128 : NH + (tile - 17) * 128;
    const int token_lim = is_h ? NTOK : (NTOT - 1);     // inclusive
    const int n0 = nb * 128;
    const __nv_bfloat16* WThi = is_h ? g_wt[0] : g_wt[2];
    const __nv_bfloat16* WTlo = is_h ? g_wt[1] : g_wt[3];
    const float* bias = is_h ? bh : bq;

    // per-thread load coordinates: row 0..127, seg 0..3 (8-element = 16B units)
    const int r = tid >> 2;
    const int seg8 = (tid & 3) * 8;
    int token_ld = tile_start + r;
    if (token_ld > NTOT - 1) token_ld = NTOT - 1;
    const long long abase = ((long long)b * NTOT + token_ld) * XD;
    const long long bbase = (long long)(n0 + r) * XD;
    const uint32_t soff = (uint32_t)(r * LDA2 + seg8) * 2;

    wmma::fragment<wmma::accumulator, 16, 16, 16, float> acc[2][2];
#pragma unroll
    for (int i = 0; i < 2; i++)
#pragma unroll
        for (int j = 0; j < 2; j++) wmma::fill_fragment(acc[i][j], 0.0f);

    // ---- pipeline: issue chunk 0
    {
        const uint32_t d = sb + soff;
        cp16(d,                      g_ahi + abase + seg8);
        cp16(d + TILE_E * 2,         g_alo + abase + seg8);
        cp16(d + 2 * TILE_E * 2,     WThi + bbase + seg8);
        cp16(d + 3 * TILE_E * 2,     WTlo + bbase + seg8);
        CP_COMMIT();
    }

    for (int ch = 0; ch < 8; ch++) {
        if (ch < 7) {
            const int k0 = (ch + 1) * KCH;
            const uint32_t d = sb + ((ch + 1) & 1) * BUF_B + soff;
            cp16(d,                  g_ahi + abase + k0 + seg8);
            cp16(d + TILE_E * 2,     g_alo + abase + k0 + seg8);
            cp16(d + 2 * TILE_E * 2, WThi + bbase + k0 + seg8);
            cp16(d + 3 * TILE_E * 2, WTlo + bbase + k0 + seg8);
            CP_COMMIT();
            CP_WAIT1();
        } else {
            CP_WAIT0();
        }
        __syncthreads();

        const __nv_bfloat16* buf = (const __nv_bfloat16*)(smem + (ch & 1) * BUF_B);
        const __nv_bfloat16* sAhi = buf;
        const __nv_bfloat16* sAlo = buf + TILE_E;
        const __nv_bfloat16* sBhi = buf + 2 * TILE_E;
        const __nv_bfloat16* sBlo = buf + 3 * TILE_E;

#pragma unroll
        for (int ks = 0; ks < 2; ks++) {
            const int ko = ks * 16;
            wmma::fragment<wmma::matrix_a, 16, 16, 16, __nv_bfloat16, wmma::row_major> aH[2], aL[2];
#pragma unroll
            for (int i = 0; i < 2; i++) {
                wmma::load_matrix_sync(aH[i], &sAhi[(wm * 32 + i * 16) * LDA2 + ko], LDA2);
                wmma::load_matrix_sync(aL[i], &sAlo[(wm * 32 + i * 16) * LDA2 + ko], LDA2);
            }
#pragma unroll
            for (int j = 0; j < 2; j++) {
                wmma::fragment<wmma::matrix_b, 16, 16, 16, __nv_bfloat16, wmma::col_major> bH, bL;
                wmma::load_matrix_sync(bH, &sBhi[(wn * 32 + j * 16) * LDA2 + ko], LDA2);
                wmma::load_matrix_sync(bL, &sBlo[(wn * 32 + j * 16) * LDA2 + ko], LDA2);
#pragma unroll
                for (int i = 0; i < 2; i++) {
                    wmma::mma_sync(acc[i][j], aH[i], bH, acc[i][j]);
                    wmma::mma_sync(acc[i][j], aH[i], bL, acc[i][j]);
                    wmma::mma_sync(acc[i][j], aL[i], bH, acc[i][j]);
                }
            }
        }
        __syncthreads();
    }

    // ---- epilogue: stage accumulators, add bias + relu, write Y
#pragma unroll
    for (int i = 0; i < 2; i++)
#pragma unroll
        for (int j = 0; j < 2; j++)
            wmma::store_matrix_sync(&stage[(wm * 32 + i * 16) * LDS_F + wn * 32 + j * 16],
                                    acc[i][j], LDS_F, wmma::mem_row_major);
    __syncthreads();

    const int token = tile_start + r;
    if (token <= token_lim) {
        const int c0 = (tid & 3) * 32;
        float* yrow = g_buf + OFF_Y + ((long long)b * NTOT + token) * HID + n0;
#pragma unroll
        for (int u = 0; u < 8; u++) {
            int c = c0 + u * 4;
            float4 v = *(float4*)&stage[r * LDS_F + c];
            float4 o;
            o.x = fmaxf(v.x + bias[n0 + c + 0], 0.f);
            o.y = fmaxf(v.y + bias[n0 + c + 1], 0.f);
            o.z = fmaxf(v.z + bias[n0 + c + 2], 0.f);
            o.w = fmaxf(v.w + bias[n0 + c + 3], 0.f);
            *(float4*)(yrow + c) = o;
        }
    }
}

// ---------------------------------------------------------------------------
// Counting sort of cs0 (deterministic)
// ---------------------------------------------------------------------------
__global__ void build_order_kernel(const int* __restrict__ cs) {
    __shared__ int s_cnt[KC];
    int tid = threadIdx.x, lane = tid & 31, w = tid >> 5;
    if (tid < KC) s_cnt[tid] = 0;
    __syncthreads();
    for (int i = tid; i < NTOK; i += blockDim.x) atomicAdd(&s_cnt[cs[i]], 1);
    __syncthreads();
    if (tid == 0) {
        int run = 0;
        for (int k = 0; k < KC; k++) {
            g_starts[k] = run; g_counts[k] = s_cnt[k];
            g_countsf[k] = (float)s_cnt[k]; run += s_cnt[k];
        }
    }
    __syncthreads();
    if (w < KC) {
        int base = g_starts[w];
        for (int i0 = 0; i0 < NTOK; i0 += 32) {
            int t = i0 + lane;
            int c = cs[t];
            unsigned m = __ballot_sync(0xffffffffu, c == w);
            if (c == w) g_order[base + __popc(m & ((1u << lane) - 1))] = t;
            base += __popc(m);
        }
    }
}

__global__ void build_rowscale_kernel() {
    int i = blockIdx.x * blockDim.x + threadIdx.x;
    if (i < ROWS_HK) {
        int k = i % (KC + 1);
        g_buf[OFF_RS + i] = (k < KC) ? g_countsf[k] : 1.0f;
    }
}

// ---------------------------------------------------------------------------
// SIMT SGEMM for small layers
// ---------------------------------------------------------------------------
#define GBM 128
#define GBN 64
#define GBK 16
__global__ void __launch_bounds__(256) sgemm_kernel(
    const float* __restrict__ Aext, long long aOff,
    const float* __restrict__ Bw, const float* __restrict__ bias,
    int useRowscale, float biasScale, long long cOff,
    int M, int N, int K, int lda, int ldb, int ldc,
    long long aStride, long long cStride, int relu)
{
    const float* A = (Aext ? Aext : (const float*)g_buf) + aOff
                     + (long long)blockIdx.z * aStride;
    float* C = g_buf + cOff + (long long)blockIdx.z * cStride;

    int tidx = threadIdx.x;
    int tx = tidx & 15;
    int ty = tidx >> 4;
    int m0 = blockIdx.y * GBM;
    int n0 = blockIdx.x * GBN;

    __shared__ float As[GBK][GBM];
    __shared__ float Bs[GBK][GBN];

    float acc[8][4];
#pragma unroll
    for (int i = 0; i < 8; i++)
#pragma unroll
        for (int j = 0; j < 4; j++) acc[i][j] = 0.0f;

    for (int k0 = 0; k0 < K; k0 += GBK) {
#pragma unroll
        for (int l = 0; l < 2; l++) {
            int idx = tidx * 2 + l;
            int r = idx >> 2;
            int kq = (idx & 3) * 4;
            float4 v = make_float4(0.f, 0.f, 0.f, 0.f);
            int m = m0 + r;
            if (m < M) v = *(const float4*)(A + (long long)m * lda + k0 + kq);
            As[kq + 0][r] = v.x; As[kq + 1][r] = v.y;
            As[kq + 2][r] = v.z; As[kq + 3][r] = v.w;
        }
        {
            int r = tidx >> 4;
            int c = (tidx & 15) * 4;
            *(float4*)&Bs[r][c] = *(const float4*)(Bw + (long long)(k0 + r) * ldb + n0 + c);
        }
        __syncthreads();
#pragma unroll
        for (int kk = 0; kk < GBK; kk++) {
            float4 a0 = *(const float4*)&As[kk][ty * 8];
            float4 a1 = *(const float4*)&As[kk][ty * 8 + 4];
            float4 b0 = *(const float4*)&Bs[kk][tx * 4];
            float a[8] = {a0.x, a0.y, a0.z, a0.w, a1.x, a1.y, a1.z, a1.w};
            float br[4] = {b0.x, b0.y, b0.z, b0.w};
#pragma unroll
            for (int i = 0; i < 8; i++)
#pragma unroll
                for (int j = 0; j < 4; j++) acc[i][j] = fmaf(a[i], br[j], acc[i][j]);
        }
        __syncthreads();
    }

    const float* rowscale = useRowscale ? (const float*)g_buf + OFF_RS : nullptr;
#pragma unroll
    for (int i = 0; i < 8; i++) {
        int m = m0 + ty * 8 + i;
        if (m >= M) continue;
        float rs = biasScale * (rowscale ? rowscale[m] : 1.0f);
#pragma unroll
        for (int j = 0; j < 4; j++) {
            int nn = n0 + tx * 4 + j;
            float v = acc[i][j];
            if (bias) v += rs * bias[nn];
            if (relu) v = fmaxf(v, 0.0f);
            C[(long long)m * ldc + nn] = v;
        }
    }
}

// ---------------------------------------------------------------------------
// Reductions / glue
// ---------------------------------------------------------------------------
__global__ void reduce_kernel() {
    int b = blockIdx.y;
    int x = blockIdx.x;
    int f = threadIdx.x;
    const float* Yb = g_buf + OFF_Y + (long long)b * NTOT * HID;

    if (x < KC) {
        int s = g_starts[x], c = g_counts[x];
        float a0 = 0.f, a1 = 0.f, a2 = 0.f, a3 = 0.f;
        int i = 0;
        for (; i + 4 <= c; i += 4) {
            a0 += Yb[(long long)g_order[s + i + 0] * HID + f];
            a1 += Yb[(long long)g_order[s + i + 1] * HID + f];
            a2 += Yb[(long long)g_order[s + i + 2] * HID + f];
            a3 += Yb[(long long)g_order[s + i + 3] * HID + f];
        }
        for (; i < c; i++) a0 += Yb[(long long)g_order[s + i] * HID + f];
        g_buf[OFF_RH + ((long long)b * (KC + 1) + x) * HID + f] = (a0 + a1) + (a2 + a3);
    } else if (x == KC) {
        g_buf[OFF_RH + ((long long)b * (KC + 1) + KC) * HID + f] =
            Yb[(long long)NTOK * HID + f];
    } else {
        int c = x - KC - 1;
        int t0 = NH + c * 256;
        int t1 = min(NTOT, t0 + 256);
        float a0 = 0.f, a1 = 0.f, a2 = 0.f, a3 = 0.f;
        int t = t0;
        for (; t + 4 <= t1; t += 4) {
            a0 += Yb[(long long)(t + 0) * HID + f];
            a1 += Yb[(long long)(t + 1) * HID + f];
            a2 += Yb[(long long)(t + 2) * HID + f];
            a3 += Yb[(long long)(t + 3) * HID + f];
        }
        for (; t < t1; t++) a0 += Yb[(long long)t * HID + f];
        g_buf[OFF_RQP + ((long long)c * BB + b) * HID + f] = (a0 + a1) + (a2 + a3);
    }
}

__global__ void reduce_q_kernel() {
    int b = blockIdx.x, f = threadIdx.x;
    float acc = 0.f;
#pragma unroll
    for (int c = 0; c < QCHUNK; c++)
        acc += g_buf[OFF_RQP + ((long long)c * BB + b) * HID + f];
    g_buf[OFF_RQ + (long long)b * HID + f] = acc;
}

__global__ void build_H_kernel() {
    int row = blockIdx.x;
    int b = row / (2 * KC + 1), j = row % (2 * KC + 1);
    int f = threadIdx.x;
    const float* Hk = g_buf + OFF_HK + (long long)b * (KC + 1) * HDIM;
    float hn = Hk[KC * HDIM + f];
    float v = (j < KC) ? Hk[j * HDIM + f]
            : (j < 2 * KC) ? Hk[(j - KC) * HDIM + f] + hn
            : hn;
    g_buf[OFF_H + (long long)row * HDIM + f] = v;
}

__global__ void compute_S_kernel() {
    int b = blockIdx.x, f = threadIdx.x;
    const float* gsb = g_buf + OFF_GS + (long long)b * (2 * KC + 1) * GDIM;
    float acc = 0.f;
#pragma unroll
    for (int k = 0; k < KC; k++) acc += gsb[(long long)k * GDIM + f];
    g_buf[OFF_S + (long long)b * GDIM + f] = acc;
}

__global__ void build_uu_kernel() {
    int row = blockIdx.x;
    int b = row / (KC + 1), j = row % (KC + 1);
    int f = threadIdx.x;
    float v;
    if (f < GDIM) {
        float S = g_buf[OFF_S + (long long)b * GDIM + f];
        const float* gsb = g_buf + OFF_GS + (long long)b * (2 * KC + 1) * GDIM;
        if (j < KC) v = S - gsb[(long long)j * GDIM + f] + gsb[(long long)(KC + j) * GDIM + f];
        else        v = S + gsb[(long long)(2 * KC) * GDIM + f];
    } else {
        v = g_buf[OFF_Q + (long long)b * HDIM + (f - GDIM)];
    }
    g_buf[OFF_UU + (long long)row * (GDIM + HDIM) + f] = v;
}

__global__ void final_kernel(const float* __restrict__ We2, float* __restrict__ out) {
    int w = (blockIdx.x * blockDim.x + threadIdx.x) >> 5;
    int lane = threadIdx.x & 31;
    if (w >= ROWS_E) return;
    const float* r = g_buf + OFF_EH + (long long)w * HID;
    float acc = 0.f;
    for (int i = lane; i < HID; i += 32) acc += r[i] * We2[i];
#pragma unroll
    for (int o = 16; o; o >>= 1) acc += __shfl_xor_sync(0xffffffffu, acc, o);
    if (lane == 0) {
        out[w] = acc;
        out[ROWS_E + w] = 1.0f;
    }
}

// ---------------------------------------------------------------------------
// Launch
// ---------------------------------------------------------------------------
static inline void launch_sgemm(const float* Aext, long long aOff,
                                const float* Bw, const float* bias,
                                int useRS, float biasScale, long long cOff,
                                int M, int N, int K, int lda, int ldb, int ldc,
                                long long aStride, long long cStride, int Z, int relu)
{
    dim3 grid(N / GBN, (M + GBM - 1) / GBM, Z);
    sgemm_kernel<<<grid, 256>>>(Aext, aOff, Bw, bias, useRS, biasScale, cOff,
                                M, N, K, lda, ldb, ldc, aStride, cStride, relu);
}

extern "C" void kernel_launch(void* const* d_in, const int* in_sizes, int n_in,
                              void* d_out, int out_size) {
    const float* data = (const float*)d_in[0];
    const int*   cs   = (const int*)  d_in[1];
    const float* Wh1 = (const float*)d_in[3];
    const float* bh1 = (const float*)d_in[4];
    const float* Wh2 = (const float*)d_in[5];
    const float* bh2 = (const float*)d_in[6];
    const float* Wq1 = (const float*)d_in[7];
    const float* bq1 = (const float*)d_in[8];
    const float* Wq2 = (const float*)d_in[9];
    const float* bq2 = (const float*)d_in[10];
    const float* Wg1 = (const float*)d_in[11];
    const float* bg1 = (const float*)d_in[12];
    const float* Wg2 = (const float*)d_in[13];
    const float* bg2 = (const float*)d_in[14];
    const float* We1 = (const float*)d_in[15];
    const float* be1 = (const float*)d_in[16];
    const float* We2 = (const float*)d_in[17];
    float* out = (float*)d_out;

    // 1) cluster counting-sort + bias row scales + weight/data split
    build_order_kernel<<<1, 1024>>>(cs);
    build_rowscale_kernel<<<(ROWS_HK + 255) / 256, 256>>>();
    prep_weights_kernel<<<(XD * HID + 255) / 256, 256>>>(Wh1, Wq1);
    prep_data_kernel<<<(int)(((long long)BB * NTOT * XD / 4 + 255) / 256), 256>>>(data);

    // 2) layer-1 wmma tensor cores, cp.async double-buffered -> Y
    cudaFuncSetAttribute(layer1_wmma_kernel,
                         cudaFuncAttributeMaxDynamicSharedMemorySize, L1_SMEM);
    layer1_wmma_kernel<<<dim3(4, 33, BB), 512, L1_SMEM>>>(bh1, bq1);

    // 3) deterministic cluster / Q reductions over Y
    reduce_kernel<<<dim3(KC + 1 + QCHUNK, BB), 512>>>();
    reduce_q_kernel<<<BB, 512>>>();

    // 4) Hk = Rh @ Wh2 + counts*bh2
    launch_sgemm(nullptr, OFF_RH, Wh2, bh2, 1, 1.0f, OFF_HK,
                 ROWS_HK, HDIM, HID, HID, HDIM, HDIM, 0, 0, 1, 0);
    // 5) Q = Rq @ Wq2 + 2047*bq2
    launch_sgemm(nullptr, OFF_RQ, Wq2, bq2, 0, (float)NQ, OFF_Q,
                 BB, HDIM, HID, HID, HDIM, HDIM, 0, 0, 1, 0);

    // 6) g-MLP on H
    build_H_kernel<<<ROWS_H, HDIM>>>();
    launch_sgemm(nullptr, OFF_H, Wg1, bg1, 0, 1.0f, OFF_G1,
                 ROWS_H, HID, HDIM, HDIM, HID, HID, 0, 0, 1, 1);
    launch_sgemm(nullptr, OFF_G1, Wg2, bg2, 0, 1.0f, OFF_GS,
                 ROWS_H, GDIM, HID, HID, GDIM, GDIM, 0, 0, 1, 0);

    // 7) combine G + Q -> uu, then energy MLP
    compute_S_kernel<<<BB, GDIM>>>();
    build_uu_kernel<<<ROWS_E, GDIM + HDIM>>>();
    launch_sgemm(nullptr, OFF_UU, We1, be1, 0, 1.0f, OFF_EH,
                 ROWS_E, HID, GDIM + HDIM, GDIM + HDIM, HID, HID, 0, 0, 1, 1);
    final_kernel<<<(ROWS_E * 32 + 255) / 256, 256>>>(We2, out);
}